// round 12
// baseline (speedup 1.0000x reference)
#include <cuda_runtime.h>
#include <math.h>

#define NN   100000
#define EE   1600000
#define MM   (EE + NN)
#define INF_ 128
#define OUTF 64

// -------- scratch (static device globals; no allocation allowed) --------
__device__ float g_hlin[(size_t)NN * OUTF];   // 25.6 MB
__device__ float g_ssrc[NN];
__device__ float g_sdst[NN];
__device__ float g_m[NN];
__device__ float g_denom[NN];
__device__ float g_e[MM];                     // edge scores -> exp values

// ---------------------------------------------------------------
// init: zero output + reset per-node max/denom (must run every call:
// graph replays re-use the same device globals)
// ---------------------------------------------------------------
__global__ void gat_init(float* __restrict__ out) {
    int i = blockIdx.x * blockDim.x + threadIdx.x;
    if (i < NN * OUTF) out[i] = 0.0f;
    if (i < NN) {
        g_m[i]     = __int_as_float(0xFF800000);  // -inf
        g_denom[i] = 0.0f;
    }
}

// ---------------------------------------------------------------
// GEMM: h_lin = h @ W^T     (N x 128) * (64 x 128)^T -> (N x 64)
// Block: 256 threads, 32 rows. W staged in smem with XOR swizzle so
// float4 reads (lane = feature) are bank-conflict free. h tile reads
// are warp-broadcast. FMA-bound (~25us target).
// ---------------------------------------------------------------
__global__ __launch_bounds__(256) void gat_gemm(const float* __restrict__ h,
                                                const float* __restrict__ W) {
    __shared__ float Ws[OUTF * INF_];   // 32 KB, swizzled [f][k]
    __shared__ float hs[32 * INF_];     // 16 KB

    const int tid = threadIdx.x;

    // stage W with XOR swizzle on the k4 group
#pragma unroll
    for (int t = 0; t < 32; t++) {
        int g  = tid + t * 256;          // 8192 floats
        int f  = g >> 7;
        int k  = g & 127;
        int k4 = k >> 2, ki = k & 3;
        Ws[(f << 7) + (((k4 ^ (f & 7)) << 2) | ki)] = W[g];
    }
    // stage h tile (32 rows x 128) -- fully coalesced float4
    {
        const float4* hg  = (const float4*)(h + (size_t)blockIdx.x * 32 * INF_);
        float4*       hsv = (float4*)hs;
#pragma unroll
        for (int t = 0; t < 4; t++) hsv[tid + t * 256] = hg[tid + t * 256];
    }
    __syncthreads();

    const int f  = tid & 63;   // output feature
    const int rg = tid >> 6;   // row group (0..3), 8 rows each
    float acc[8] = {0.f, 0.f, 0.f, 0.f, 0.f, 0.f, 0.f, 0.f};

#pragma unroll
    for (int k4 = 0; k4 < 32; k4++) {
        float4 wv = *(const float4*)&Ws[(f << 7) + ((k4 ^ (f & 7)) << 2)];
#pragma unroll
        for (int j = 0; j < 8; j++) {
            float4 hv = *(const float4*)&hs[(rg * 8 + j) * INF_ + k4 * 4];
            acc[j] += hv.x * wv.x + hv.y * wv.y + hv.z * wv.z + hv.w * wv.w;
        }
    }

    size_t row0 = (size_t)blockIdx.x * 32 + rg * 8;
#pragma unroll
    for (int j = 0; j < 8; j++)
        g_hlin[(row0 + j) * OUTF + f] = acc[j];
}

// ---------------------------------------------------------------
// s_src = h_lin @ a1, s_dst = h_lin @ a2   (one warp per row)
// ---------------------------------------------------------------
__global__ __launch_bounds__(256) void gat_scores(const float* __restrict__ a) {
    const int wid  = threadIdx.x >> 5;
    const int lane = threadIdx.x & 31;
    const int row  = blockIdx.x * 8 + wid;

    const float* hl = g_hlin + (size_t)row * OUTF;
    float h0 = hl[lane], h1 = hl[lane + 32];
    float s1 = h0 * a[lane]      + h1 * a[lane + 32];
    float s2 = h0 * a[64 + lane] + h1 * a[96 + lane];
#pragma unroll
    for (int o = 16; o; o >>= 1) {
        s1 += __shfl_xor_sync(0xFFFFFFFFu, s1, o);
        s2 += __shfl_xor_sync(0xFFFFFFFFu, s2, o);
    }
    if (lane == 0) { g_ssrc[row] = s1; g_sdst[row] = s2; }
}

// ---------------------------------------------------------------
// pass A: e = leakyrelu(s_src[row] + s_dst[col]); segment max via
// float atomic max (signed-max for >=0, unsigned-min for <0; init -inf)
// ---------------------------------------------------------------
__global__ void gat_edge_max(const int* __restrict__ ei) {
    int i = blockIdx.x * blockDim.x + threadIdx.x;
    if (i >= MM) return;
    int r, c;
    if (i < EE) { r = ei[i]; c = ei[EE + i]; }
    else        { r = c = i - EE; }
    float e = g_ssrc[r] + g_sdst[c];
    e = (e > 0.0f) ? e : 0.2f * e;
    g_e[i] = e;
    if (e >= 0.0f) atomicMax((int*)&g_m[r], __float_as_int(e));
    else           atomicMin((unsigned int*)&g_m[r], __float_as_uint(e));
}

// ---------------------------------------------------------------
// pass B: ex = exp(e - m[row]); denom[row] += ex  (ex cached in g_e)
// ---------------------------------------------------------------
__global__ void gat_edge_exp(const int* __restrict__ ei) {
    int i = blockIdx.x * blockDim.x + threadIdx.x;
    if (i >= MM) return;
    int r = (i < EE) ? ei[i] : i - EE;
    float ex = __expf(g_e[i] - g_m[r]);
    g_e[i] = ex;
    atomicAdd(&g_denom[r], ex);
}

// ---------------------------------------------------------------
// pass C: out[row] += (ex/denom[row]) * h_lin[col]
// 16 lanes per edge, each lane does one red.global.add.v4.f32 (16B).
// gathers & atomics all L2-resident.
// ---------------------------------------------------------------
__global__ __launch_bounds__(256) void gat_scatter(const int* __restrict__ ei,
                                                   float* __restrict__ out) {
    int gt  = blockIdx.x * 256 + threadIdx.x;   // up to 27.2M < 2^31
    int eid = gt >> 4;
    int sub = gt & 15;
    if (eid >= MM) return;
    int r, c;
    if (eid < EE) { r = ei[eid]; c = ei[EE + eid]; }
    else          { r = c = eid - EE; }
    float alpha = g_e[eid] / g_denom[r];
    float4 v = *(const float4*)&g_hlin[(size_t)c * OUTF + sub * 4];
    v.x *= alpha; v.y *= alpha; v.z *= alpha; v.w *= alpha;
    float* p = out + (size_t)r * OUTF + sub * 4;
    asm volatile("red.global.add.v4.f32 [%0], {%1, %2, %3, %4};"
                 :: "l"(p), "f"(v.x), "f"(v.y), "f"(v.z), "f"(v.w)
                 : "memory");
}

// ---------------------------------------------------------------
// elu in place (expm1f matches jax.nn.elu exactly near 0)
// ---------------------------------------------------------------
__global__ void gat_elu(float* __restrict__ out) {
    int i = blockIdx.x * blockDim.x + threadIdx.x;
    if (i < NN * OUTF) {
        float x = out[i];
        out[i] = (x > 0.0f) ? x : expm1f(x);
    }
}

// ---------------------------------------------------------------
// inputs (metadata order): h [N*128 f32], W [64*128 f32], a [128 f32],
// edge_index [2*E int32]. output: [N*64 f32]
// ---------------------------------------------------------------
extern "C" void kernel_launch(void* const* d_in, const int* in_sizes, int n_in,
                              void* d_out, int out_size) {
    (void)in_sizes; (void)n_in; (void)out_size;
    const float* h  = (const float*)d_in[0];
    const float* W  = (const float*)d_in[1];
    const float* a  = (const float*)d_in[2];
    const int*   ei = (const int*)d_in[3];
    float* out = (float*)d_out;

    gat_init<<<(NN * OUTF + 255) / 256, 256>>>(out);
    gat_gemm<<<NN / 32, 256>>>(h, W);
    gat_scores<<<NN / 8, 256>>>(a);
    gat_edge_max<<<(MM + 255) / 256, 256>>>(ei);
    gat_edge_exp<<<(MM + 255) / 256, 256>>>(ei);
    gat_scatter<<<MM / 16, 256>>>(ei, out);   // MM*16/256 = MM/16 exactly
    gat_elu<<<(NN * OUTF + 255) / 256, 256>>>(out);
}

// round 13
// speedup vs baseline: 1.0058x; 1.0058x over previous
#include <cuda_runtime.h>
#include <math.h>

#define NN   100000
#define EE   1600000
#define MM   (EE + NN)
#define INF_ 128
#define OUTF 64

// -------- scratch (static device globals; no allocation allowed) --------
__device__ float g_hlin[(size_t)NN * OUTF];   // 25.6 MB
__device__ float g_ssrc[NN];
__device__ float g_sdst[NN];
__device__ float g_m[NN];
__device__ float g_denom[NN];
__device__ float g_e[MM];                     // edge scores -> exp values

// ---------------------------------------------------------------
// init: zero output + reset per-node max/denom (must run every call:
// graph replays re-use the same device globals)
// ---------------------------------------------------------------
__global__ void gat_init(float* __restrict__ out) {
    int i = blockIdx.x * blockDim.x + threadIdx.x;
    if (i < NN * OUTF) out[i] = 0.0f;
    if (i < NN) {
        g_m[i]     = __int_as_float(0xFF800000);  // -inf
        g_denom[i] = 0.0f;
    }
}

// ---------------------------------------------------------------
// GEMM: h_lin = h @ W^T     (N x 128) * (64 x 128)^T -> (N x 64)
// Block: 256 threads, 32 rows. W staged in smem with XOR swizzle so
// float4 reads (lane = feature) are bank-conflict free. h tile reads
// are warp-broadcast. FMA-bound (~25us target).
// ---------------------------------------------------------------
__global__ __launch_bounds__(256) void gat_gemm(const float* __restrict__ h,
                                                const float* __restrict__ W) {
    __shared__ float Ws[OUTF * INF_];   // 32 KB, swizzled [f][k]
    __shared__ float hs[32 * INF_];     // 16 KB

    const int tid = threadIdx.x;

    // stage W with XOR swizzle on the k4 group
#pragma unroll
    for (int t = 0; t < 32; t++) {
        int g  = tid + t * 256;          // 8192 floats
        int f  = g >> 7;
        int k  = g & 127;
        int k4 = k >> 2, ki = k & 3;
        Ws[(f << 7) + (((k4 ^ (f & 7)) << 2) | ki)] = W[g];
    }
    // stage h tile (32 rows x 128) -- fully coalesced float4
    {
        const float4* hg  = (const float4*)(h + (size_t)blockIdx.x * 32 * INF_);
        float4*       hsv = (float4*)hs;
#pragma unroll
        for (int t = 0; t < 4; t++) hsv[tid + t * 256] = hg[tid + t * 256];
    }
    __syncthreads();

    const int f  = tid & 63;   // output feature
    const int rg = tid >> 6;   // row group (0..3), 8 rows each
    float acc[8] = {0.f, 0.f, 0.f, 0.f, 0.f, 0.f, 0.f, 0.f};

#pragma unroll
    for (int k4 = 0; k4 < 32; k4++) {
        float4 wv = *(const float4*)&Ws[(f << 7) + ((k4 ^ (f & 7)) << 2)];
#pragma unroll
        for (int j = 0; j < 8; j++) {
            float4 hv = *(const float4*)&hs[(rg * 8 + j) * INF_ + k4 * 4];
            acc[j] += hv.x * wv.x + hv.y * wv.y + hv.z * wv.z + hv.w * wv.w;
        }
    }

    size_t row0 = (size_t)blockIdx.x * 32 + rg * 8;
#pragma unroll
    for (int j = 0; j < 8; j++)
        g_hlin[(row0 + j) * OUTF + f] = acc[j];
}

// ---------------------------------------------------------------
// s_src = h_lin @ a1, s_dst = h_lin @ a2   (one warp per row)
// ---------------------------------------------------------------
__global__ __launch_bounds__(256) void gat_scores(const float* __restrict__ a) {
    const int wid  = threadIdx.x >> 5;
    const int lane = threadIdx.x & 31;
    const int row  = blockIdx.x * 8 + wid;

    const float* hl = g_hlin + (size_t)row * OUTF;
    float h0 = hl[lane], h1 = hl[lane + 32];
    float s1 = h0 * a[lane]      + h1 * a[lane + 32];
    float s2 = h0 * a[64 + lane] + h1 * a[96 + lane];
#pragma unroll
    for (int o = 16; o; o >>= 1) {
        s1 += __shfl_xor_sync(0xFFFFFFFFu, s1, o);
        s2 += __shfl_xor_sync(0xFFFFFFFFu, s2, o);
    }
    if (lane == 0) { g_ssrc[row] = s1; g_sdst[row] = s2; }
}

// ---------------------------------------------------------------
// pass A: e = leakyrelu(s_src[row] + s_dst[col]); segment max via
// float atomic max (signed-max for >=0, unsigned-min for <0; init -inf)
// ---------------------------------------------------------------
__global__ void gat_edge_max(const int* __restrict__ ei) {
    int i = blockIdx.x * blockDim.x + threadIdx.x;
    if (i >= MM) return;
    int r, c;
    if (i < EE) { r = ei[i]; c = ei[EE + i]; }
    else        { r = c = i - EE; }
    float e = g_ssrc[r] + g_sdst[c];
    e = (e > 0.0f) ? e : 0.2f * e;
    g_e[i] = e;
    if (e >= 0.0f) atomicMax((int*)&g_m[r], __float_as_int(e));
    else           atomicMin((unsigned int*)&g_m[r], __float_as_uint(e));
}

// ---------------------------------------------------------------
// pass B: ex = exp(e - m[row]); denom[row] += ex  (ex cached in g_e)
// ---------------------------------------------------------------
__global__ void gat_edge_exp(const int* __restrict__ ei) {
    int i = blockIdx.x * blockDim.x + threadIdx.x;
    if (i >= MM) return;
    int r = (i < EE) ? ei[i] : i - EE;
    float ex = __expf(g_e[i] - g_m[r]);
    g_e[i] = ex;
    atomicAdd(&g_denom[r], ex);
}

// ---------------------------------------------------------------
// pass C: out[row] += (ex/denom[row]) * h_lin[col]
// 16 lanes per edge, each lane does one red.global.add.v4.f32 (16B).
// gathers & atomics all L2-resident.
// ---------------------------------------------------------------
__global__ __launch_bounds__(256) void gat_scatter(const int* __restrict__ ei,
                                                   float* __restrict__ out) {
    int gt  = blockIdx.x * 256 + threadIdx.x;   // up to 27.2M < 2^31
    int eid = gt >> 4;
    int sub = gt & 15;
    if (eid >= MM) return;
    int r, c;
    if (eid < EE) { r = ei[eid]; c = ei[EE + eid]; }
    else          { r = c = eid - EE; }
    float alpha = g_e[eid] / g_denom[r];
    float4 v = *(const float4*)&g_hlin[(size_t)c * OUTF + sub * 4];
    v.x *= alpha; v.y *= alpha; v.z *= alpha; v.w *= alpha;
    float* p = out + (size_t)r * OUTF + sub * 4;
    asm volatile("red.global.add.v4.f32 [%0], {%1, %2, %3, %4};"
                 :: "l"(p), "f"(v.x), "f"(v.y), "f"(v.z), "f"(v.w)
                 : "memory");
}

// ---------------------------------------------------------------
// elu in place (expm1f matches jax.nn.elu exactly near 0)
// ---------------------------------------------------------------
__global__ void gat_elu(float* __restrict__ out) {
    int i = blockIdx.x * blockDim.x + threadIdx.x;
    if (i < NN * OUTF) {
        float x = out[i];
        out[i] = (x > 0.0f) ? x : expm1f(x);
    }
}

// ---------------------------------------------------------------
// inputs (metadata order): h [N*128 f32], W [64*128 f32], a [128 f32],
// edge_index [2*E int32]. output: [N*64 f32]
// ---------------------------------------------------------------
extern "C" void kernel_launch(void* const* d_in, const int* in_sizes, int n_in,
                              void* d_out, int out_size) {
    (void)in_sizes; (void)n_in; (void)out_size;
    const float* h  = (const float*)d_in[0];
    const float* W  = (const float*)d_in[1];
    const float* a  = (const float*)d_in[2];
    const int*   ei = (const int*)d_in[3];
    float* out = (float*)d_out;

    gat_init<<<(NN * OUTF + 255) / 256, 256>>>(out);
    gat_gemm<<<NN / 32, 256>>>(h, W);
    gat_scores<<<NN / 8, 256>>>(a);
    gat_edge_max<<<(MM + 255) / 256, 256>>>(ei);
    gat_edge_exp<<<(MM + 255) / 256, 256>>>(ei);
    gat_scatter<<<MM / 16, 256>>>(ei, out);   // MM*16/256 = MM/16 exactly
    gat_elu<<<(NN * OUTF + 255) / 256, 256>>>(out);
}